// round 9
// baseline (speedup 1.0000x reference)
#include <cuda_runtime.h>
#include <math.h>

#define DIM 64
#define FIN 32
#define MAXN 50048
#define MAXE 60032
#define MAXB 256
#define ELLW 16
#define CAP 320
#define FS 65

#define ADS 136    // duplicated activation stride: [64 k][64 nodes x2]
#define WAST 66    // EW out-major stride
#define W2ST 392   // packed gate weight stride (32 dpairs * 12 + pad)

typedef unsigned long long ull;

// ---------------- device scratch ----------------
__device__ float g_ew[DIM * DIM];
__device__ float g_feat2[MAXN * DIM];
__device__ int   g_deg[MAXN];
__device__ int   g_ell[MAXN * ELLW];
__device__ float g_e[MAXN];
__device__ int   g_gstart[MAXB + 1];

__device__ __forceinline__ float sigmoidf_(float x) { return 1.0f / (1.0f + __expf(-x)); }

__device__ __forceinline__ ull ffma2(ull a, ull b, ull c) {
    ull d;
    asm("fma.rn.f32x2 %0, %1, %2, %3;" : "=l"(d) : "l"(a), "l"(b), "l"(c));
    return d;
}
__device__ __forceinline__ float2 unpack2(ull v) {
    float2 f;
    asm("mov.b64 {%0, %1}, %2;" : "=f"(f.x), "=f"(f.y) : "l"(v));
    return f;
}

// ============ launch 0: EW + zero deg + init gstart ============
__global__ void k_init(const float* __restrict__ nn1_w, const float* __restrict__ nn1_b,
                       const float* __restrict__ nn2_w, const float* __restrict__ nn2_b,
                       int N, int B) {
    int i = blockIdx.x * blockDim.x + threadIdx.x;
    if (i < DIM * DIM) {
        float acc = nn2_b[i];
        const float* row = &nn2_w[i * DIM];
#pragma unroll 8
        for (int dd = 0; dd < DIM; dd++)
            acc += fmaxf(nn1_w[dd] + nn1_b[dd], 0.0f) * row[dd];
        g_ew[i] = acc;
    }
    if (i < N) g_deg[i] = 0;
    if (i <= B) g_gstart[i] = N;
}

// ============ launch 1: ELL insert + mark graph starts ============
__global__ void k_count(const int* __restrict__ src, const int* __restrict__ dst,
                        const int* __restrict__ batch, int E, int N) {
    int i = blockIdx.x * blockDim.x + threadIdx.x;
    if (i < E) {
        int dn = dst[i];
        int slot = atomicAdd(&g_deg[dn], 1);
        if (slot < ELLW) g_ell[dn * ELLW + slot] = src[i];
    }
    if (i < N) {
        if (i == 0 || batch[i - 1] != batch[i]) atomicMin(&g_gstart[batch[i]], i);
    }
}

// ============ launch 2: lin0 (+ gstart monotone fix in block 0) ============
__global__ void k_lin0(const float* __restrict__ x, const float* __restrict__ w,
                       const float* __restrict__ b, float* __restrict__ feat, int N, int B) {
    __shared__ float sw[DIM * 33];
    __shared__ float sb[DIM];
    __shared__ float sx[16 * FIN];
    int t = threadIdx.x;
    if (blockIdx.x == 0 && t == 0) {
        g_gstart[B] = N;
        for (int bb = B - 1; bb >= 0; bb--)
            if (g_gstart[bb] > g_gstart[bb + 1]) g_gstart[bb] = g_gstart[bb + 1];
    }
    for (int i = t; i < DIM * FIN; i += 256) sw[(i >> 5) * 33 + (i & 31)] = w[i];
    if (t < DIM) sb[t] = b[t];
    __syncthreads();
    int d = t & 63, tq = t >> 6;
    for (int tile = blockIdx.x * 16; tile < N; tile += gridDim.x * 16) {
        for (int i = t; i < 16 * FIN; i += 256) {
            int n = tile + (i >> 5);
            sx[i] = (n < N) ? x[n * FIN + (i & 31)] : 0.0f;
        }
        __syncthreads();
#pragma unroll
        for (int k = 0; k < 4; k++) {
            int loc = tq * 4 + k;
            int n = tile + loc;
            if (n < N) {
                float acc = sb[d];
                const float* xr = &sx[loc * FIN];
#pragma unroll
                for (int f = 0; f < FIN; f++) acc += xr[f] * sw[d * 33 + f];
                feat[n * DIM + d] = fmaxf(acc, 0.0f);
            }
        }
        __syncthreads();
    }
}

// ============ fused gather + NNConv + GRU: FFMA2 over dim-pairs, dup activations ============
// smem (floats)
#define OFF_WA 0                               // [64 k][WAST] EW out-major
#define OFF_W2 (64 * WAST)                     // 4224: [64 k][W2ST] packed gate weights
#define OFF_S  (OFF_W2 + 64 * W2ST)            // 29312: [64 k][ADS] dup
#define OFF_H  (OFF_S + 64 * ADS)              // 38016
#define OFF_M  (OFF_H + 64 * ADS)              // 46720
#define SMEM_ITER_FLOATS (OFF_M + 64 * ADS)    // 55424 floats = 216.5 KB

__global__ void __launch_bounds__(512, 1)
k_iter(const float* __restrict__ fin, float* __restrict__ fout,
       const float* __restrict__ wih, const float* __restrict__ whh,
       const float* __restrict__ bih, const float* __restrict__ bhh,
       const float* __restrict__ convb, int N) {
    extern __shared__ float sm[];
    float* sWa = sm + OFF_WA;
    float* sW2 = sm + OFF_W2;
    float* sS  = sm + OFF_S;
    float* sH  = sm + OFF_H;
    float* sM  = sm + OFF_M;

    int t = threadIdx.x;
    // EW out-major [k][d]
    for (int i = t; i < DIM * DIM; i += 512) {
        int k = i >> 6, d = i & 63;
        sWa[k * WAST + d] = g_ew[i];
    }
    // packed gate weights: [k][dp*12 + slot]; slots: wr0 wr1 wz0 wz1 | wn0 wn1 vr0 vr1 | vz0 vz1 vn0 vn1
    for (int i = t; i < 3 * DIM * DIM; i += 512) {
        int row = i >> 6, k = i & 63;          // row = gate*64 + d
        int g = row >> 6, d = row & 63;
        int dp = d >> 1, dd = d & 1;
        sW2[k * W2ST + dp * 12 + g * 2 + dd]     = wih[i];
        sW2[k * W2ST + dp * 12 + 6 + g * 2 + dd] = whh[i];
    }
    __syncthreads();

    int w = t >> 5, ln = t & 31;
    int d63 = t & 63, q8 = (t >> 6) * 8;

    // stage A thread mapping: warp w -> dims 4w..4w+3; lanes: 16 node-groups x 2 dpairs
    int ngA = ln & 15, dpgA = ln >> 4;
    int d0A = 4 * w + 2 * dpgA;
    float cbA0 = convb[d0A], cbA1 = convb[d0A + 1];

    // gates mapping: warp: node-half x dim-group(8 dims); lanes: 8 node-groups x 4 dpairs
    int nh = w & 1, dg = w >> 1;
    int ngB = ln & 7, dpgB = ln >> 3;
    int d0 = 8 * dg + 2 * dpgB;
    int nb = nh * 64 + 8 * ngB;                // dup-index base (nodes nh*32+4ngB ..+3)
    float br0 = bih[d0] + bhh[d0],           br1 = bih[d0 + 1] + bhh[d0 + 1];
    float bz0 = bih[64 + d0] + bhh[64 + d0], bz1 = bih[64 + d0 + 1] + bhh[64 + d0 + 1];
    float bni0 = bih[128 + d0], bni1 = bih[128 + d0 + 1];
    float bnh0 = bhh[128 + d0], bnh1 = bhh[128 + d0 + 1];

    for (int tile = blockIdx.x * 64; tile < N; tile += gridDim.x * 64) {
        // ---- gather: 8 nodes per thread (column d63), store DUPLICATED (v,v)
#pragma unroll
        for (int j = 0; j < 8; j++) {
            int n = tile + q8 + j;
            float s = 0.0f, h = 0.0f;
            if (n < N) {
                h = fin[n * DIM + d63];
                int dgc = g_deg[n]; if (dgc > ELLW) dgc = ELLW;
                const int* er = &g_ell[n * ELLW];
                for (int e = 0; e < dgc; e++) s += fin[er[e] * DIM + d63];
                s *= (dgc > 0) ? (1.0f / (float)dgc) : 0.0f;
            }
            *(float2*)&sS[d63 * ADS + 2 * (q8 + j)] = make_float2(s, s);
            *(float2*)&sH[d63 * ADS + 2 * (q8 + j)] = make_float2(h, h);
        }
        __syncthreads();

        // ---- stage A: m = relu(s @ EW + cb); thread: 4 nodes x 1 dpair, FFMA2
        {
            ull a0 = 0, a1 = 0, a2 = 0, a3 = 0;
            const float* Sp = &sS[8 * ngA];
            const float* Wp = &sWa[d0A];
#pragma unroll 4
            for (int k = 0; k < 64; k++) {
                ulonglong2 s01 = *(const ulonglong2*)&Sp[k * ADS];
                ulonglong2 s23 = *(const ulonglong2*)&Sp[k * ADS + 4];
                ull wv = *(const ull*)&Wp[k * WAST];
                a0 = ffma2(s01.x, wv, a0); a1 = ffma2(s01.y, wv, a1);
                a2 = ffma2(s23.x, wv, a2); a3 = ffma2(s23.y, wv, a3);
            }
            ull aa[4] = {a0, a1, a2, a3};
#pragma unroll
            for (int j = 0; j < 4; j++) {
                float2 u = unpack2(aa[j]);
                float m0 = fmaxf(u.x + cbA0, 0.0f);
                float m1 = fmaxf(u.y + cbA1, 0.0f);
                int nn2 = 2 * (4 * ngA + j);
                *(float2*)&sM[d0A * ADS + nn2]       = make_float2(m0, m0);
                *(float2*)&sM[(d0A + 1) * ADS + nn2] = make_float2(m1, m1);
            }
        }
        __syncthreads();

        // ---- gates: thread: 4 nodes x 1 dpair x 6 matvecs, FFMA2, no packing
        {
            ull aR[4] = {0,0,0,0}, aZ[4] = {0,0,0,0}, aN[4] = {0,0,0,0};
            ull hR[4] = {0,0,0,0}, hZ[4] = {0,0,0,0}, hN[4] = {0,0,0,0};
            const float* Wp2 = &sW2[12 * (4 * dg + dpgB)];
            const float* Mp = &sM[nb];
            const float* Hp = &sH[nb];
#pragma unroll 2
            for (int k = 0; k < 64; k++) {
                const float* wk = &Wp2[k * W2ST];
                float4 w0 = *(const float4*)&wk[0];
                float4 w1 = *(const float4*)&wk[4];
                float4 w2 = *(const float4*)&wk[8];
                ull uwr = ((const ull*)&w0)[0], uwz = ((const ull*)&w0)[1];
                ull uwn = ((const ull*)&w1)[0], uvr = ((const ull*)&w1)[1];
                ull uvz = ((const ull*)&w2)[0], uvn = ((const ull*)&w2)[1];
                ulonglong2 m01 = *(const ulonglong2*)&Mp[k * ADS];
                ulonglong2 m23 = *(const ulonglong2*)&Mp[k * ADS + 4];
                ulonglong2 h01 = *(const ulonglong2*)&Hp[k * ADS];
                ulonglong2 h23 = *(const ulonglong2*)&Hp[k * ADS + 4];
                aR[0] = ffma2(m01.x, uwr, aR[0]); aR[1] = ffma2(m01.y, uwr, aR[1]);
                aR[2] = ffma2(m23.x, uwr, aR[2]); aR[3] = ffma2(m23.y, uwr, aR[3]);
                aZ[0] = ffma2(m01.x, uwz, aZ[0]); aZ[1] = ffma2(m01.y, uwz, aZ[1]);
                aZ[2] = ffma2(m23.x, uwz, aZ[2]); aZ[3] = ffma2(m23.y, uwz, aZ[3]);
                aN[0] = ffma2(m01.x, uwn, aN[0]); aN[1] = ffma2(m01.y, uwn, aN[1]);
                aN[2] = ffma2(m23.x, uwn, aN[2]); aN[3] = ffma2(m23.y, uwn, aN[3]);
                hR[0] = ffma2(h01.x, uvr, hR[0]); hR[1] = ffma2(h01.y, uvr, hR[1]);
                hR[2] = ffma2(h23.x, uvr, hR[2]); hR[3] = ffma2(h23.y, uvr, hR[3]);
                hZ[0] = ffma2(h01.x, uvz, hZ[0]); hZ[1] = ffma2(h01.y, uvz, hZ[1]);
                hZ[2] = ffma2(h01.y * 0 + h23.x, uvz, hZ[2]); hZ[3] = ffma2(h23.y, uvz, hZ[3]);
                hN[0] = ffma2(h01.x, uvn, hN[0]); hN[1] = ffma2(h01.y, uvn, hN[1]);
                hN[2] = ffma2(h23.x, uvn, hN[2]); hN[3] = ffma2(h23.y, uvn, hN[3]);
            }
#pragma unroll
            for (int j = 0; j < 4; j++) {
                int n = tile + nh * 32 + 4 * ngB + j;
                if (n < N) {
                    float2 ur = unpack2(aR[j]), uz = unpack2(aZ[j]), un = unpack2(aN[j]);
                    float2 vr = unpack2(hR[j]), vz = unpack2(hZ[j]), vn = unpack2(hN[j]);
                    float h0 = sH[d0 * ADS + nb + 2 * j];
                    float h1 = sH[(d0 + 1) * ADS + nb + 2 * j];
                    float r0 = sigmoidf_(ur.x + vr.x + br0);
                    float z0 = sigmoidf_(uz.x + vz.x + bz0);
                    float g0 = tanhf(un.x + bni0 + r0 * (vn.x + bnh0));
                    float o0 = (1.0f - z0) * g0 + z0 * h0;
                    float r1 = sigmoidf_(ur.y + vr.y + br1);
                    float z1 = sigmoidf_(uz.y + vz.y + bz1);
                    float g1 = tanhf(un.y + bni1 + r1 * (vn.y + bnh1));
                    float o1 = (1.0f - z1) * g1 + z1 * h1;
                    *(float2*)&fout[n * DIM + d0] = make_float2(o0, o1);
                }
            }
        }
        __syncthreads();
    }
}

// ============ fused Set2Set with smem feature cache ============
#define S2_F 0
#define S2_E (S2_F + CAP * FS)
#define S2_RED (S2_E + CAP)
#define S2_GATE (S2_RED + 256)
#define S2_Q (S2_GATE + 256)
#define S2_HL (S2_Q + 128)
#define S2_CL (S2_HL + 64)
#define SMEM_S2S_FLOATS (S2_CL + 64)

__global__ void __launch_bounds__(256, 1)
k_set2set(const float* __restrict__ feat,
          const float* __restrict__ wih, const float* __restrict__ whh,
          const float* __restrict__ bih, const float* __restrict__ bhh,
          float* __restrict__ out) {
    extern __shared__ float sm[];
    float* sF = sm + S2_F;
    float* sE = sm + S2_E;
    float* sRed = sm + S2_RED;
    float* sGate = sm + S2_GATE;
    float* sQ = sm + S2_Q;
    float* sHl = sm + S2_HL;
    float* sCl = sm + S2_CL;

    int b = blockIdx.x, t = threadIdx.x;
    int s0 = g_gstart[b], s1 = g_gstart[b + 1], cnt = s1 - s0;
    int cc = (cnt < CAP) ? cnt : CAP;
    for (int i = t; i < cc * DIM; i += 256) {
        int j = i >> 6, d = i & 63;
        sF[j * FS + d] = feat[(s0 + j) * DIM + d];
    }
    if (t < 128) sQ[t] = 0.0f;
    if (t < 64) { sHl[t] = 0.0f; sCl[t] = 0.0f; }
    __syncthreads();

    for (int step = 0; step < 3; step++) {
        {
            float acc = bih[t] + bhh[t];
            const float* wr = &wih[t * 2 * DIM];
#pragma unroll
            for (int j = 0; j < 2 * DIM; j += 4) {
                float4 w = *(const float4*)&wr[j];
                float4 q = *(const float4*)&sQ[j];
                acc += w.x * q.x + w.y * q.y + w.z * q.z + w.w * q.w;
            }
            const float* vr = &whh[t * DIM];
#pragma unroll
            for (int j = 0; j < DIM; j += 4) {
                float4 w = *(const float4*)&vr[j];
                float4 h = *(const float4*)&sHl[j];
                acc += w.x * h.x + w.y * h.y + w.z * h.z + w.w * h.w;
            }
            sGate[t] = acc;
        }
        __syncthreads();
        if (t < 64) {
            float ig = sigmoidf_(sGate[t]);
            float fg = sigmoidf_(sGate[64 + t]);
            float gg = tanhf(sGate[128 + t]);
            float og = sigmoidf_(sGate[192 + t]);
            float c = fg * sCl[t] + ig * gg;
            sCl[t] = c;
            sHl[t] = og * tanhf(c);
        }
        __syncthreads();

        float mx = -1e30f;
        for (int j = t; j < cnt; j += 256) {
            float v = 0.0f;
            if (j < CAP) {
                const float* fr = &sF[j * FS];
#pragma unroll 8
                for (int dd = 0; dd < DIM; dd++) v += fr[dd] * sHl[dd];
                sE[j] = v;
            } else {
                const float* fr = &feat[(s0 + j) * DIM];
                for (int dd = 0; dd < DIM; dd++) v += fr[dd] * sHl[dd];
                g_e[s0 + j] = v;
            }
            mx = fmaxf(mx, v);
        }
        sRed[t] = mx;
        __syncthreads();
        for (int off = 128; off > 0; off >>= 1) {
            if (t < off) sRed[t] = fmaxf(sRed[t], sRed[t + off]);
            __syncthreads();
        }
        float emax = (cnt > 0) ? sRed[0] : 0.0f;
        __syncthreads();

        float sme = 0.0f;
        for (int j = t; j < cnt; j += 256) {
            float e = (j < CAP) ? sE[j] : g_e[s0 + j];
            sme += __expf(e - emax);
        }
        sRed[t] = sme;
        __syncthreads();
        for (int off = 128; off > 0; off >>= 1) {
            if (t < off) sRed[t] += sRed[t + off];
            __syncthreads();
        }
        float scale = 1.0f / (sRed[0] + 1e-16f);
        __syncthreads();
        for (int j = t; j < cnt; j += 256) {
            if (j < CAP) sE[j] = __expf(sE[j] - emax) * scale;
            else g_e[s0 + j] = __expf(g_e[s0 + j] - emax) * scale;
        }
        __syncthreads();

        {
            int d = t & 63, q = t >> 6;
            float acc = 0.0f;
            for (int j = q; j < cnt; j += 4) {
                float a = (j < CAP) ? sE[j] : g_e[s0 + j];
                float fv = (j < CAP) ? sF[j * FS + d] : feat[(s0 + j) * DIM + d];
                acc += a * fv;
            }
            sRed[t] = acc;
        }
        __syncthreads();
        if (t < 64) {
            float r = sRed[t] + sRed[64 + t] + sRed[128 + t] + sRed[192 + t];
            if (step == 2) {
                out[b * 2 * DIM + t] = sHl[t];
                out[b * 2 * DIM + DIM + t] = r;
            } else {
                sQ[t] = sHl[t];
                sQ[DIM + t] = r;
            }
        }
        __syncthreads();
    }
}

// ---------------- launch ----------------
extern "C" void kernel_launch(void* const* d_in, const int* in_sizes, int n_in,
                              void* d_out, int out_size) {
    const float* x        = (const float*)d_in[0];
    const int*   ei       = (const int*)d_in[1];
    const int*   batch    = (const int*)d_in[2];
    const float* lin0_w   = (const float*)d_in[3];
    const float* lin0_b   = (const float*)d_in[4];
    const float* nn1_w    = (const float*)d_in[5];
    const float* nn1_b    = (const float*)d_in[6];
    const float* nn2_w    = (const float*)d_in[7];
    const float* nn2_b    = (const float*)d_in[8];
    const float* conv_b   = (const float*)d_in[9];
    const float* gru_w_ih = (const float*)d_in[10];
    const float* gru_w_hh = (const float*)d_in[11];
    const float* gru_b_ih = (const float*)d_in[12];
    const float* gru_b_hh = (const float*)d_in[13];
    const float* lstm_w_ih = (const float*)d_in[14];
    const float* lstm_w_hh = (const float*)d_in[15];
    const float* lstm_b_ih = (const float*)d_in[16];
    const float* lstm_b_hh = (const float*)d_in[17];

    int N = in_sizes[2];
    int E = in_sizes[1] / 2;
    int B = (out_size - N * DIM) / (2 * DIM);

    float* out  = (float*)d_out;
    float* feat = out + B * 2 * DIM;

    float* feat2 = nullptr;
    cudaGetSymbolAddress((void**)&feat2, g_feat2);

    const int* src = ei;
    const int* dst = ei + E;

    const size_t smem_iter = SMEM_ITER_FLOATS * sizeof(float);
    const size_t smem_s2s  = SMEM_S2S_FLOATS * sizeof(float);
    cudaFuncSetAttribute(k_iter, cudaFuncAttributeMaxDynamicSharedMemorySize, (int)smem_iter);
    cudaFuncSetAttribute(k_set2set, cudaFuncAttributeMaxDynamicSharedMemorySize, (int)smem_s2s);

    int mx1 = (N > DIM * DIM ? N : DIM * DIM);
    int mx2 = (E > N ? E : N);

    // 0: EW + zero deg + gstart init
    k_init<<<(mx1 + 1023) / 1024, 1024>>>(nn1_w, nn1_b, nn2_w, nn2_b, N, B);
    // 1: ELL adjacency insert + graph-start marks
    k_count<<<(mx2 + 1023) / 1024, 1024>>>(src, dst, batch, E, N);
    // 2: lin0 (+ gstart fix)
    k_lin0<<<148, 256>>>(x, lin0_w, lin0_b, feat2, N, B);

    // 3..5: fused gather + NNConv + GRU  (index 3 gets profiled)
    k_iter<<<148, 512, smem_iter>>>(feat2, feat, gru_w_ih, gru_w_hh, gru_b_ih, gru_b_hh, conv_b, N);
    k_iter<<<148, 512, smem_iter>>>(feat, feat2, gru_w_ih, gru_w_hh, gru_b_ih, gru_b_hh, conv_b, N);
    k_iter<<<148, 512, smem_iter>>>(feat2, feat, gru_w_ih, gru_w_hh, gru_b_ih, gru_b_hh, conv_b, N);

    // 6: fused Set2Set
    k_set2set<<<B, 256, smem_s2s>>>(feat, lstm_w_ih, lstm_w_hh, lstm_b_ih, lstm_b_hh, out);
}

// round 10
// speedup vs baseline: 1.5043x; 1.5043x over previous
#include <cuda_runtime.h>
#include <math.h>

#define DIM 64
#define FIN 32
#define MAXN 50048
#define MAXE 60032
#define MAXB 256
#define ELLW 16
#define CAP 320
#define FS 65

#define AST 68      // activation array stride (k-major [64 k][64 n + pad])
#define WAST 68     // stage A weight stride
#define W2ST 388    // packed gate weight stride (32 dpairs * 12 + pad)

// ---------------- device scratch ----------------
__device__ float g_ew[DIM * DIM];
__device__ float g_feat2[MAXN * DIM];
__device__ int   g_deg[MAXN];
__device__ int   g_ell[MAXN * ELLW];
__device__ float g_e[MAXN];
__device__ int   g_gstart[MAXB + 1];

// fast transcendentals: MUFU.EX2 + MUFU.RCP based (rel err ~1e-6, budget 1e-3)
__device__ __forceinline__ float fsig(float x) {
    return __fdividef(1.0f, 1.0f + __expf(-x));
}
__device__ __forceinline__ float ftanh(float x) {
    float e = __expf(2.0f * x);
    return __fdividef(e - 1.0f, e + 1.0f);
}

// ============ launch 0: EW + zero deg + init gstart ============
__global__ void k_init(const float* __restrict__ nn1_w, const float* __restrict__ nn1_b,
                       const float* __restrict__ nn2_w, const float* __restrict__ nn2_b,
                       int N, int B) {
    int i = blockIdx.x * blockDim.x + threadIdx.x;
    if (i < DIM * DIM) {
        float acc = nn2_b[i];
        const float* row = &nn2_w[i * DIM];
#pragma unroll 8
        for (int dd = 0; dd < DIM; dd++)
            acc += fmaxf(nn1_w[dd] + nn1_b[dd], 0.0f) * row[dd];
        g_ew[i] = acc;
    }
    if (i < N) g_deg[i] = 0;
    if (i <= B) g_gstart[i] = N;
}

// ============ launch 1: ELL insert + mark graph starts ============
__global__ void k_count(const int* __restrict__ src, const int* __restrict__ dst,
                        const int* __restrict__ batch, int E, int N) {
    int i = blockIdx.x * blockDim.x + threadIdx.x;
    if (i < E) {
        int dn = dst[i];
        int slot = atomicAdd(&g_deg[dn], 1);
        if (slot < ELLW) g_ell[dn * ELLW + slot] = src[i];
    }
    if (i < N) {
        if (i == 0 || batch[i - 1] != batch[i]) atomicMin(&g_gstart[batch[i]], i);
    }
}

// ============ launch 2: lin0 (+ gstart monotone fix in block 0) ============
__global__ void k_lin0(const float* __restrict__ x, const float* __restrict__ w,
                       const float* __restrict__ b, float* __restrict__ feat, int N, int B) {
    __shared__ float sw[DIM * 33];
    __shared__ float sb[DIM];
    __shared__ float sx[16 * FIN];
    int t = threadIdx.x;
    if (blockIdx.x == 0 && t == 0) {
        g_gstart[B] = N;
        for (int bb = B - 1; bb >= 0; bb--)
            if (g_gstart[bb] > g_gstart[bb + 1]) g_gstart[bb] = g_gstart[bb + 1];
    }
    for (int i = t; i < DIM * FIN; i += 256) sw[(i >> 5) * 33 + (i & 31)] = w[i];
    if (t < DIM) sb[t] = b[t];
    __syncthreads();
    int d = t & 63, tq = t >> 6;
    for (int tile = blockIdx.x * 16; tile < N; tile += gridDim.x * 16) {
        for (int i = t; i < 16 * FIN; i += 256) {
            int n = tile + (i >> 5);
            sx[i] = (n < N) ? x[n * FIN + (i & 31)] : 0.0f;
        }
        __syncthreads();
#pragma unroll
        for (int k = 0; k < 4; k++) {
            int loc = tq * 4 + k;
            int n = tile + loc;
            if (n < N) {
                float acc = sb[d];
                const float* xr = &sx[loc * FIN];
#pragma unroll
                for (int f = 0; f < FIN; f++) acc += xr[f] * sw[d * 33 + f];
                feat[n * DIM + d] = fmaxf(acc, 0.0f);
            }
        }
        __syncthreads();
    }
}

// ============ fused gather + NNConv + GRU: warp = 64 nodes, dims split across warps ============
// smem (floats)
#define OFF_WA  0                               // [64 k][WAST]  EW k-major
#define OFF_W2  (64 * WAST)                     // 4352: [64 k][W2ST] packed gate weights
#define OFF_S   (OFF_W2 + 64 * W2ST)            // 29184: 2 x [64 k][AST]
#define OFF_M   (OFF_S + 2 * 64 * AST)          // 37888: 1 x [64 d][AST]
#define OFF_H   (OFF_M + 64 * AST)              // 42240: 2 x [64 d][AST]
#define OFF_CB  (OFF_H + 2 * 64 * AST)          // 50944
#define OFF_BIH (OFF_CB + 64)
#define OFF_BHH (OFF_BIH + 192)
#define SMEM_ITER_FLOATS (OFF_BHH + 192)        // 51392 floats = 200.75 KB

__device__ __forceinline__ void gather8(const float* __restrict__ fin, int tile, int q8,
                                        int d63, int N, float* sv, float* hv) {
#pragma unroll
    for (int j = 0; j < 8; j++) {
        int n = tile + q8 + j;
        float s = 0.0f, h = 0.0f;
        if (n < N) {
            h = fin[n * DIM + d63];
            int dg = g_deg[n]; if (dg > ELLW) dg = ELLW;
            const int* er = &g_ell[n * ELLW];
            for (int e = 0; e < dg; e++) s += fin[er[e] * DIM + d63];
            s *= (dg > 0) ? __fdividef(1.0f, (float)dg) : 0.0f;
        }
        sv[j] = s; hv[j] = h;
    }
}

__global__ void __launch_bounds__(512, 1)
k_iter(const float* __restrict__ fin, float* __restrict__ fout,
       const float* __restrict__ wih, const float* __restrict__ whh,
       const float* __restrict__ bih, const float* __restrict__ bhh,
       const float* __restrict__ convb, int N) {
    extern __shared__ float sm[];
    float* sWa  = sm + OFF_WA;
    float* sW2  = sm + OFF_W2;
    float* sS   = sm + OFF_S;
    float* sM   = sm + OFF_M;
    float* sH   = sm + OFF_H;
    float* sCb  = sm + OFF_CB;
    float* sBih = sm + OFF_BIH;
    float* sBhh = sm + OFF_BHH;

    int t = threadIdx.x;
    // EW k-major
    for (int i = t; i < DIM * DIM; i += 512) {
        int k = i >> 6, d = i & 63;
        sWa[k * WAST + d] = g_ew[i];
    }
    // packed gate weights: [k][dp*12 + slot]; slots: wr0 wr1 wz0 wz1 wn0 wn1 vr0 vr1 vz0 vz1 vn0 vn1
    for (int i = t; i < 3 * DIM * DIM; i += 512) {
        int row = i >> 6, k = i & 63;          // row 0..191 = gate*64 + d
        int g = row >> 6, d = row & 63;
        int dp = d >> 1, dd = d & 1;
        sW2[k * W2ST + dp * 12 + g * 2 + dd]     = wih[i];
        sW2[k * W2ST + dp * 12 + 6 + g * 2 + dd] = whh[i];
    }
    if (t < 64) sCb[t] = convb[t];
    if (t < 192) { sBih[t] = bih[t]; sBhh[t] = bhh[t]; }
    __syncthreads();

    int w = t >> 5, ln = t & 31;
    int d63 = t & 63, q8 = (t >> 6) * 8;
    int step = gridDim.x * 64;

    float sv[8], hv[8];
    int tile0 = blockIdx.x * 64;
    if (tile0 < N) gather8(fin, tile0, q8, d63, N, sv, hv);

    int buf = 0;
    for (int tile = tile0; tile < N; tile += step) {
        // ---- commit prefetched gather (float4, k-major rows)
        {
            float* Sb = sS + buf * (64 * AST);
            float* Hb = sH + buf * (64 * AST);
            *(float4*)&Sb[d63 * AST + q8]     = make_float4(sv[0], sv[1], sv[2], sv[3]);
            *(float4*)&Sb[d63 * AST + q8 + 4] = make_float4(sv[4], sv[5], sv[6], sv[7]);
            *(float4*)&Hb[d63 * AST + q8]     = make_float4(hv[0], hv[1], hv[2], hv[3]);
            *(float4*)&Hb[d63 * AST + q8 + 4] = make_float4(hv[4], hv[5], hv[6], hv[7]);
        }
        __syncthreads();

        // ---- prefetch next tile (overlaps compute)
        int nxt = tile + step;
        if (nxt < N) gather8(fin, nxt, q8, d63, N, sv, hv);

        const float* Sb = sS + buf * (64 * AST);
        const float* Hb = sH + buf * (64 * AST);

        // ---- stage A: warp w -> dims 4w..4w+3, all 64 nodes (lane: nodes 2ln,2ln+1)
        {
            int d0 = w * 4;
            float a[4][2] = {{0,0},{0,0},{0,0},{0,0}};
            const float* Wp = &sWa[d0];
            const float* Sp = &Sb[2 * ln];
#pragma unroll 8
            for (int k = 0; k < 64; k++) {
                float2 s2 = *(const float2*)&Sp[k * AST];
                float4 w4 = *(const float4*)&Wp[k * WAST];
                a[0][0] += w4.x * s2.x; a[0][1] += w4.x * s2.y;
                a[1][0] += w4.y * s2.x; a[1][1] += w4.y * s2.y;
                a[2][0] += w4.z * s2.x; a[2][1] += w4.z * s2.y;
                a[3][0] += w4.w * s2.x; a[3][1] += w4.w * s2.y;
            }
#pragma unroll
            for (int dd = 0; dd < 4; dd++) {
                float cb = sCb[d0 + dd];
                *(float2*)&sM[(d0 + dd) * AST + 2 * ln] =
                    make_float2(fmaxf(a[dd][0] + cb, 0.0f), fmaxf(a[dd][1] + cb, 0.0f));
            }
        }
        __syncthreads();

        // ---- stage B: 2 passes; warp owns dim-pair dp, all 64 nodes
#pragma unroll
        for (int p = 0; p < 2; p++) {
            int dp = w + 16 * p;               // 0..31
            int d0 = dp * 2;
            float air[2][2] = {{0,0},{0,0}}, aiz[2][2] = {{0,0},{0,0}}, ain[2][2] = {{0,0},{0,0}};
            float ahr[2][2] = {{0,0},{0,0}}, ahz[2][2] = {{0,0},{0,0}}, ahn[2][2] = {{0,0},{0,0}};
            const float* Wp = &sW2[dp * 12];
            const float* Mp = &sM[2 * ln];
            const float* Hp = &Hb[2 * ln];
#pragma unroll 8
            for (int k = 0; k < 64; k++) {
                float2 mp = *(const float2*)&Mp[k * AST];
                float2 hp = *(const float2*)&Hp[k * AST];
                const float* wk = &Wp[k * W2ST];
                float4 w0 = *(const float4*)&wk[0];   // wr0 wr1 wz0 wz1
                float4 w1 = *(const float4*)&wk[4];   // wn0 wn1 vr0 vr1
                float4 w2 = *(const float4*)&wk[8];   // vz0 vz1 vn0 vn1
                air[0][0] += w0.x * mp.x; air[0][1] += w0.x * mp.y;
                air[1][0] += w0.y * mp.x; air[1][1] += w0.y * mp.y;
                aiz[0][0] += w0.z * mp.x; aiz[0][1] += w0.z * mp.y;
                aiz[1][0] += w0.w * mp.x; aiz[1][1] += w0.w * mp.y;
                ain[0][0] += w1.x * mp.x; ain[0][1] += w1.x * mp.y;
                ain[1][0] += w1.y * mp.x; ain[1][1] += w1.y * mp.y;
                ahr[0][0] += w1.z * hp.x; ahr[0][1] += w1.z * hp.y;
                ahr[1][0] += w1.w * hp.x; ahr[1][1] += w1.w * hp.y;
                ahz[0][0] += w2.x * hp.x; ahz[0][1] += w2.x * hp.y;
                ahz[1][0] += w2.y * hp.x; ahz[1][1] += w2.y * hp.y;
                ahn[0][0] += w2.z * hp.x; ahn[0][1] += w2.z * hp.y;
                ahn[1][0] += w2.w * hp.x; ahn[1][1] += w2.w * hp.y;
            }
#pragma unroll
            for (int dd = 0; dd < 2; dd++) {
                int d = d0 + dd;
                float br = sBih[d] + sBhh[d];
                float bz = sBih[64 + d] + sBhh[64 + d];
                float bn_i = sBih[128 + d];
                float bn_h = sBhh[128 + d];
#pragma unroll
                for (int nn = 0; nn < 2; nn++) {
                    int n = tile + 2 * ln + nn;
                    if (n < N) {
                        float r = fsig(air[dd][nn] + ahr[dd][nn] + br);
                        float z = fsig(aiz[dd][nn] + ahz[dd][nn] + bz);
                        float g = ftanh(ain[dd][nn] + bn_i + r * (ahn[dd][nn] + bn_h));
                        float h0 = Hb[d * AST + 2 * ln + nn];
                        fout[n * DIM + d] = (1.0f - z) * g + z * h0;
                    }
                }
            }
        }
        buf ^= 1;
    }
}

// ============ fused Set2Set with smem feature cache ============
#define S2_F 0
#define S2_E (S2_F + CAP * FS)
#define S2_RED (S2_E + CAP)
#define S2_GATE (S2_RED + 256)
#define S2_Q (S2_GATE + 256)
#define S2_HL (S2_Q + 128)
#define S2_CL (S2_HL + 64)
#define SMEM_S2S_FLOATS (S2_CL + 64)

__global__ void __launch_bounds__(256, 1)
k_set2set(const float* __restrict__ feat,
          const float* __restrict__ wih, const float* __restrict__ whh,
          const float* __restrict__ bih, const float* __restrict__ bhh,
          float* __restrict__ out) {
    extern __shared__ float sm[];
    float* sF = sm + S2_F;
    float* sE = sm + S2_E;
    float* sRed = sm + S2_RED;
    float* sGate = sm + S2_GATE;
    float* sQ = sm + S2_Q;
    float* sHl = sm + S2_HL;
    float* sCl = sm + S2_CL;

    int b = blockIdx.x, t = threadIdx.x;
    int s0 = g_gstart[b], s1 = g_gstart[b + 1], cnt = s1 - s0;
    int cc = (cnt < CAP) ? cnt : CAP;
    for (int i = t; i < cc * DIM; i += 256) {
        int j = i >> 6, d = i & 63;
        sF[j * FS + d] = feat[(s0 + j) * DIM + d];
    }
    if (t < 128) sQ[t] = 0.0f;
    if (t < 64) { sHl[t] = 0.0f; sCl[t] = 0.0f; }
    __syncthreads();

    for (int step = 0; step < 3; step++) {
        {
            float acc = bih[t] + bhh[t];
            const float* wr = &wih[t * 2 * DIM];
#pragma unroll
            for (int j = 0; j < 2 * DIM; j += 4) {
                float4 w = *(const float4*)&wr[j];
                float4 q = *(const float4*)&sQ[j];
                acc += w.x * q.x + w.y * q.y + w.z * q.z + w.w * q.w;
            }
            const float* vr = &whh[t * DIM];
#pragma unroll
            for (int j = 0; j < DIM; j += 4) {
                float4 w = *(const float4*)&vr[j];
                float4 h = *(const float4*)&sHl[j];
                acc += w.x * h.x + w.y * h.y + w.z * h.z + w.w * h.w;
            }
            sGate[t] = acc;
        }
        __syncthreads();
        if (t < 64) {
            float ig = fsig(sGate[t]);
            float fg = fsig(sGate[64 + t]);
            float gg = ftanh(sGate[128 + t]);
            float og = fsig(sGate[192 + t]);
            float c = fg * sCl[t] + ig * gg;
            sCl[t] = c;
            sHl[t] = og * ftanh(c);
        }
        __syncthreads();

        float mx = -1e30f;
        for (int j = t; j < cnt; j += 256) {
            float v = 0.0f;
            if (j < CAP) {
                const float* fr = &sF[j * FS];
#pragma unroll 8
                for (int dd = 0; dd < DIM; dd++) v += fr[dd] * sHl[dd];
                sE[j] = v;
            } else {
                const float* fr = &feat[(s0 + j) * DIM];
                for (int dd = 0; dd < DIM; dd++) v += fr[dd] * sHl[dd];
                g_e[s0 + j] = v;
            }
            mx = fmaxf(mx, v);
        }
        sRed[t] = mx;
        __syncthreads();
        for (int off = 128; off > 0; off >>= 1) {
            if (t < off) sRed[t] = fmaxf(sRed[t], sRed[t + off]);
            __syncthreads();
        }
        float emax = (cnt > 0) ? sRed[0] : 0.0f;
        __syncthreads();

        float sme = 0.0f;
        for (int j = t; j < cnt; j += 256) {
            float e = (j < CAP) ? sE[j] : g_e[s0 + j];
            sme += __expf(e - emax);
        }
        sRed[t] = sme;
        __syncthreads();
        for (int off = 128; off > 0; off >>= 1) {
            if (t < off) sRed[t] += sRed[t + off];
            __syncthreads();
        }
        float scale = __fdividef(1.0f, sRed[0] + 1e-16f);
        __syncthreads();
        for (int j = t; j < cnt; j += 256) {
            if (j < CAP) sE[j] = __expf(sE[j] - emax) * scale;
            else g_e[s0 + j] = __expf(g_e[s0 + j] - emax) * scale;
        }
        __syncthreads();

        {
            int d = t & 63, q = t >> 6;
            float acc = 0.0f;
            for (int j = q; j < cnt; j += 4) {
                float a = (j < CAP) ? sE[j] : g_e[s0 + j];
                float fv = (j < CAP) ? sF[j * FS + d] : feat[(s0 + j) * DIM + d];
                acc += a * fv;
            }
            sRed[t] = acc;
        }
        __syncthreads();
        if (t < 64) {
            float r = sRed[t] + sRed[64 + t] + sRed[128 + t] + sRed[192 + t];
            if (step == 2) {
                out[b * 2 * DIM + t] = sHl[t];
                out[b * 2 * DIM + DIM + t] = r;
            } else {
                sQ[t] = sHl[t];
                sQ[DIM + t] = r;
            }
        }
        __syncthreads();
    }
}

// ---------------- launch ----------------
extern "C" void kernel_launch(void* const* d_in, const int* in_sizes, int n_in,
                              void* d_out, int out_size) {
    const float* x        = (const float*)d_in[0];
    const int*   ei       = (const int*)d_in[1];
    const int*   batch    = (const int*)d_in[2];
    const float* lin0_w   = (const float*)d_in[3];
    const float* lin0_b   = (const float*)d_in[4];
    const float* nn1_w    = (const float*)d_in[5];
    const float* nn1_b    = (const float*)d_in[6];
    const float* nn2_w    = (const float*)d_in[7];
    const float* nn2_b    = (const float*)d_in[8];
    const float* conv_b   = (const float*)d_in[9];
    const float* gru_w_ih = (const float*)d_in[10];
    const float* gru_w_hh = (const float*)d_in[11];
    const float* gru_b_ih = (const float*)d_in[12];
    const float* gru_b_hh = (const float*)d_in[13];
    const float* lstm_w_ih = (const float*)d_in[14];
    const float* lstm_w_hh = (const float*)d_in[15];
    const float* lstm_b_ih = (const float*)d_in[16];
    const float* lstm_b_hh = (const float*)d_in[17];

    int N = in_sizes[2];
    int E = in_sizes[1] / 2;
    int B = (out_size - N * DIM) / (2 * DIM);

    float* out  = (float*)d_out;
    float* feat = out + B * 2 * DIM;

    float* feat2 = nullptr;
    cudaGetSymbolAddress((void**)&feat2, g_feat2);

    const int* src = ei;
    const int* dst = ei + E;

    const size_t smem_iter = SMEM_ITER_FLOATS * sizeof(float);
    const size_t smem_s2s  = SMEM_S2S_FLOATS * sizeof(float);
    cudaFuncSetAttribute(k_iter, cudaFuncAttributeMaxDynamicSharedMemorySize, (int)smem_iter);
    cudaFuncSetAttribute(k_set2set, cudaFuncAttributeMaxDynamicSharedMemorySize, (int)smem_s2s);

    int mx1 = (N > DIM * DIM ? N : DIM * DIM);
    int mx2 = (E > N ? E : N);

    // 0: EW + zero deg + gstart init
    k_init<<<(mx1 + 1023) / 1024, 1024>>>(nn1_w, nn1_b, nn2_w, nn2_b, N, B);
    // 1: ELL adjacency insert + graph-start marks
    k_count<<<(mx2 + 1023) / 1024, 1024>>>(src, dst, batch, E, N);
    // 2: lin0 (+ gstart fix)
    k_lin0<<<148, 256>>>(x, lin0_w, lin0_b, feat2, N, B);

    // 3..5: fused gather + NNConv + GRU  (index 3 gets profiled)
    k_iter<<<148, 512, smem_iter>>>(feat2, feat, gru_w_ih, gru_w_hh, gru_b_ih, gru_b_hh, conv_b, N);
    k_iter<<<148, 512, smem_iter>>>(feat, feat2, gru_w_ih, gru_w_hh, gru_b_ih, gru_b_hh, conv_b, N);
    k_iter<<<148, 512, smem_iter>>>(feat2, feat, gru_w_ih, gru_w_hh, gru_b_ih, gru_b_hh, conv_b, N);

    // 6: fused Set2Set
    k_set2set<<<B, 256, smem_s2s>>>(feat, lstm_w_ih, lstm_w_hh, lstm_b_ih, lstm_b_hh, out);
}

// round 11
// speedup vs baseline: 1.5227x; 1.0122x over previous
#include <cuda_runtime.h>
#include <math.h>

#define DIM 64
#define FIN 32
#define MAXN 50048
#define MAXE 60032
#define MAXB 256
#define ELLW 16
#define CAP 320
#define FS 65

#define AST 68      // activation stride (k-major [64 k][64 n + pad])
#define WAST 68     // stage A weight stride
#define W2ST 388    // packed gate weight stride (32 dpairs * 12 + pad), mult of 4

// ---------------- device scratch ----------------
__device__ float g_ew[DIM * DIM];
__device__ float g_feat2[MAXN * DIM];
__device__ int   g_deg[MAXN];
__device__ int   g_ell[MAXN * ELLW];
__device__ float g_e[MAXN];
__device__ int   g_gstart[MAXB + 1];

__device__ __forceinline__ float fsig(float x) {
    return __fdividef(1.0f, 1.0f + __expf(-x));
}
__device__ __forceinline__ float ftanh(float x) {
    float e = __expf(2.0f * x);
    return __fdividef(e - 1.0f, e + 1.0f);
}

// ============ launch 0: EW + zero deg + init gstart ============
__global__ void k_init(const float* __restrict__ nn1_w, const float* __restrict__ nn1_b,
                       const float* __restrict__ nn2_w, const float* __restrict__ nn2_b,
                       int N, int B) {
    int i = blockIdx.x * blockDim.x + threadIdx.x;
    if (i < DIM * DIM) {
        float acc = nn2_b[i];
        const float* row = &nn2_w[i * DIM];
#pragma unroll 8
        for (int dd = 0; dd < DIM; dd++)
            acc += fmaxf(nn1_w[dd] + nn1_b[dd], 0.0f) * row[dd];
        g_ew[i] = acc;
    }
    if (i < N) g_deg[i] = 0;
    if (i <= B) g_gstart[i] = N;
}

// ============ launch 1: ELL insert + mark graph starts ============
__global__ void k_count(const int* __restrict__ src, const int* __restrict__ dst,
                        const int* __restrict__ batch, int E, int N) {
    int i = blockIdx.x * blockDim.x + threadIdx.x;
    if (i < E) {
        int dn = dst[i];
        int slot = atomicAdd(&g_deg[dn], 1);
        if (slot < ELLW) g_ell[dn * ELLW + slot] = src[i];
    }
    if (i < N) {
        if (i == 0 || batch[i - 1] != batch[i]) atomicMin(&g_gstart[batch[i]], i);
    }
}

// ============ launch 2: lin0 (+ gstart monotone fix in block 0) ============
__global__ void k_lin0(const float* __restrict__ x, const float* __restrict__ w,
                       const float* __restrict__ b, float* __restrict__ feat, int N, int B) {
    __shared__ float sw[DIM * 33];
    __shared__ float sb[DIM];
    __shared__ float sx[16 * FIN];
    int t = threadIdx.x;
    if (blockIdx.x == 0 && t == 0) {
        g_gstart[B] = N;
        for (int bb = B - 1; bb >= 0; bb--)
            if (g_gstart[bb] > g_gstart[bb + 1]) g_gstart[bb] = g_gstart[bb + 1];
    }
    for (int i = t; i < DIM * FIN; i += 256) sw[(i >> 5) * 33 + (i & 31)] = w[i];
    if (t < DIM) sb[t] = b[t];
    __syncthreads();
    int d = t & 63, tq = t >> 6;
    for (int tile = blockIdx.x * 16; tile < N; tile += gridDim.x * 16) {
        for (int i = t; i < 16 * FIN; i += 256) {
            int n = tile + (i >> 5);
            sx[i] = (n < N) ? x[n * FIN + (i & 31)] : 0.0f;
        }
        __syncthreads();
#pragma unroll
        for (int k = 0; k < 4; k++) {
            int loc = tq * 4 + k;
            int n = tile + loc;
            if (n < N) {
                float acc = sb[d];
                const float* xr = &sx[loc * FIN];
#pragma unroll
                for (int f = 0; f < FIN; f++) acc += xr[f] * sw[d * 33 + f];
                feat[n * DIM + d] = fmaxf(acc, 0.0f);
            }
        }
        __syncthreads();
    }
}

// ============ fused gather + NNConv + GRU: 1024 threads, 2-pass gates ============
// smem (floats)
#define OFF_WA  0                               // [64 k][WAST] EW k-major
#define OFF_W2  (64 * WAST)                     // 4352: [64 k][W2ST] packed gate weights
#define OFF_S   (OFF_W2 + 64 * W2ST)            // 29184: 2 x [64 k][AST]
#define OFF_H   (OFF_S + 2 * 64 * AST)          // 37888: 2 x [64 k][AST]
#define OFF_M   (OFF_H + 2 * 64 * AST)          // 46592: 2 x [64 d][AST]
#define OFF_CB  (OFF_M + 2 * 64 * AST)          // 55296
#define OFF_BIH (OFF_CB + 64)
#define OFF_BHH (OFF_BIH + 192)
#define SMEM_ITER_FLOATS (OFF_BHH + 192)        // 55744 floats = 217.75 KB

__global__ void __launch_bounds__(1024, 1)
k_iter(const float* __restrict__ fin, float* __restrict__ fout,
       const float* __restrict__ wih, const float* __restrict__ whh,
       const float* __restrict__ bih, const float* __restrict__ bhh,
       const float* __restrict__ convb, int N) {
    extern __shared__ float sm[];
    float* sWa  = sm + OFF_WA;
    float* sW2  = sm + OFF_W2;
    float* sS   = sm + OFF_S;
    float* sH   = sm + OFF_H;
    float* sM   = sm + OFF_M;
    float* sCb  = sm + OFF_CB;
    float* sBih = sm + OFF_BIH;
    float* sBhh = sm + OFF_BHH;

    int t = threadIdx.x;
    // EW k-major
    for (int i = t; i < DIM * DIM; i += 1024) {
        int k = i >> 6, d = i & 63;
        sWa[k * WAST + d] = g_ew[i];
    }
    // packed gate weights per (k, dpair):
    //   slots [0..5]  = wr0 wr1 wz0 wz1 wn0 wn1   (input pass)
    //   slots [6..11] = vr0 vr1 vz0 vz1 vn0 vn1   (hidden pass)
    for (int i = t; i < 3 * DIM * DIM; i += 1024) {
        int row = i >> 6, k = i & 63;          // row = gate*64 + d
        int g = row >> 6, d = row & 63;
        int dp = d >> 1, dd = d & 1;
        sW2[k * W2ST + dp * 12 + g * 2 + dd]     = wih[i];
        sW2[k * W2ST + dp * 12 + 6 + g * 2 + dd] = whh[i];
    }
    if (t < 64) sCb[t] = convb[t];
    if (t < 192) { sBih[t] = bih[t]; sBhh[t] = bhh[t]; }
    __syncthreads();

    int w = t >> 5, ln = t & 31;       // 32 warps; lane owns nodes 2ln, 2ln+1
    int d63 = t & 63, g4 = (t >> 6) * 4;

    int buf = 0;
    for (int tile = blockIdx.x * 64; tile < N; tile += gridDim.x * 64) {
        float* Sb = sS + buf * (64 * AST);
        float* Hb = sH + buf * (64 * AST);
        float* Mb = sM + buf * (64 * AST);

        // ---- gather: 4 nodes per thread (column d63)
        {
            float sv[4], hv[4];
#pragma unroll
            for (int j = 0; j < 4; j++) {
                int n = tile + g4 + j;
                float s = 0.0f, h = 0.0f;
                if (n < N) {
                    h = fin[n * DIM + d63];
                    int dg = g_deg[n]; if (dg > ELLW) dg = ELLW;
                    const int* er = &g_ell[n * ELLW];
                    for (int e = 0; e < dg; e++) s += fin[er[e] * DIM + d63];
                    s *= (dg > 0) ? __fdividef(1.0f, (float)dg) : 0.0f;
                }
                sv[j] = s; hv[j] = h;
            }
            *(float4*)&Sb[d63 * AST + g4] = make_float4(sv[0], sv[1], sv[2], sv[3]);
            *(float4*)&Hb[d63 * AST + g4] = make_float4(hv[0], hv[1], hv[2], hv[3]);
        }
        __syncthreads();

        // ---- stage A: warp w -> dims 2w, 2w+1; lane -> nodes 2ln, 2ln+1
        {
            int d0 = 2 * w;
            float a00 = 0.f, a01 = 0.f, a10 = 0.f, a11 = 0.f;
            const float* Wp = &sWa[d0];
            const float* Sp = &Sb[2 * ln];
#pragma unroll 8
            for (int k = 0; k < 64; k++) {
                float2 s2 = *(const float2*)&Sp[k * AST];
                float2 w2 = *(const float2*)&Wp[k * WAST];
                a00 += w2.x * s2.x; a01 += w2.x * s2.y;
                a10 += w2.y * s2.x; a11 += w2.y * s2.y;
            }
            float cb0 = sCb[d0], cb1 = sCb[d0 + 1];
            *(float2*)&Mb[d0 * AST + 2 * ln] =
                make_float2(fmaxf(a00 + cb0, 0.0f), fmaxf(a01 + cb0, 0.0f));
            *(float2*)&Mb[(d0 + 1) * AST + 2 * ln] =
                make_float2(fmaxf(a10 + cb1, 0.0f), fmaxf(a11 + cb1, 0.0f));
        }
        __syncthreads();

        // ---- stage B: warp w = dim-pair w; two gate passes
        {
            int dp = w, d0 = 2 * dp;
            const float* Wk = &sW2[dp * 12];
            // pass 1: input gates over M
            float air[2][2] = {{0,0},{0,0}}, aiz[2][2] = {{0,0},{0,0}}, ain[2][2] = {{0,0},{0,0}};
            {
                const float* Mp = &Mb[2 * ln];
#pragma unroll 8
                for (int k = 0; k < 64; k++) {
                    float2 m2 = *(const float2*)&Mp[k * AST];
                    float4 wA = *(const float4*)&Wk[k * W2ST];       // wr0 wr1 wz0 wz1
                    float2 wB = *(const float2*)&Wk[k * W2ST + 4];   // wn0 wn1
                    air[0][0] += wA.x * m2.x; air[0][1] += wA.x * m2.y;
                    air[1][0] += wA.y * m2.x; air[1][1] += wA.y * m2.y;
                    aiz[0][0] += wA.z * m2.x; aiz[0][1] += wA.z * m2.y;
                    aiz[1][0] += wA.w * m2.x; aiz[1][1] += wA.w * m2.y;
                    ain[0][0] += wB.x * m2.x; ain[0][1] += wB.x * m2.y;
                    ain[1][0] += wB.y * m2.x; ain[1][1] += wB.y * m2.y;
                }
            }
            // pass 2: hidden gates over H
            float ahr[2][2] = {{0,0},{0,0}}, ahz[2][2] = {{0,0},{0,0}}, ahn[2][2] = {{0,0},{0,0}};
            {
                const float* Hp = &Hb[2 * ln];
#pragma unroll 8
                for (int k = 0; k < 64; k++) {
                    float2 h2 = *(const float2*)&Hp[k * AST];
                    float2 vA = *(const float2*)&Wk[k * W2ST + 6];   // vr0 vr1
                    float4 vB = *(const float4*)&Wk[k * W2ST + 8];   // vz0 vz1 vn0 vn1
                    ahr[0][0] += vA.x * h2.x; ahr[0][1] += vA.x * h2.y;
                    ahr[1][0] += vA.y * h2.x; ahr[1][1] += vA.y * h2.y;
                    ahz[0][0] += vB.x * h2.x; ahz[0][1] += vB.x * h2.y;
                    ahz[1][0] += vB.y * h2.x; ahz[1][1] += vB.y * h2.y;
                    ahn[0][0] += vB.z * h2.x; ahn[0][1] += vB.z * h2.y;
                    ahn[1][0] += vB.w * h2.x; ahn[1][1] += vB.w * h2.y;
                }
            }
            // epilogue: 2 dims x 2 nodes per thread
#pragma unroll
            for (int dd = 0; dd < 2; dd++) {
                int d = d0 + dd;
                float br = sBih[d] + sBhh[d];
                float bz = sBih[64 + d] + sBhh[64 + d];
                float bn_i = sBih[128 + d];
                float bn_h = sBhh[128 + d];
#pragma unroll
                for (int nn = 0; nn < 2; nn++) {
                    int n = tile + 2 * ln + nn;
                    if (n < N) {
                        float r = fsig(air[dd][nn] + ahr[dd][nn] + br);
                        float z = fsig(aiz[dd][nn] + ahz[dd][nn] + bz);
                        float g = ftanh(ain[dd][nn] + bn_i + r * (ahn[dd][nn] + bn_h));
                        float h0 = Hb[d * AST + 2 * ln + nn];
                        fout[n * DIM + d] = (1.0f - z) * g + z * h0;
                    }
                }
            }
        }
        buf ^= 1;   // S/H/M double-buffered: no end-of-loop barrier needed
    }
}

// ============ fused Set2Set with smem feature cache ============
#define S2_F 0
#define S2_E (S2_F + CAP * FS)
#define S2_RED (S2_E + CAP)
#define S2_GATE (S2_RED + 256)
#define S2_Q (S2_GATE + 256)
#define S2_HL (S2_Q + 128)
#define S2_CL (S2_HL + 64)
#define SMEM_S2S_FLOATS (S2_CL + 64)

__global__ void __launch_bounds__(256, 1)
k_set2set(const float* __restrict__ feat,
          const float* __restrict__ wih, const float* __restrict__ whh,
          const float* __restrict__ bih, const float* __restrict__ bhh,
          float* __restrict__ out) {
    extern __shared__ float sm[];
    float* sF = sm + S2_F;
    float* sE = sm + S2_E;
    float* sRed = sm + S2_RED;
    float* sGate = sm + S2_GATE;
    float* sQ = sm + S2_Q;
    float* sHl = sm + S2_HL;
    float* sCl = sm + S2_CL;

    int b = blockIdx.x, t = threadIdx.x;
    int s0 = g_gstart[b], s1 = g_gstart[b + 1], cnt = s1 - s0;
    int cc = (cnt < CAP) ? cnt : CAP;
    for (int i = t; i < cc * DIM; i += 256) {
        int j = i >> 6, d = i & 63;
        sF[j * FS + d] = feat[(s0 + j) * DIM + d];
    }
    if (t < 128) sQ[t] = 0.0f;
    if (t < 64) { sHl[t] = 0.0f; sCl[t] = 0.0f; }
    __syncthreads();

    for (int step = 0; step < 3; step++) {
        {
            float acc = bih[t] + bhh[t];
            const float* wr = &wih[t * 2 * DIM];
#pragma unroll
            for (int j = 0; j < 2 * DIM; j += 4) {
                float4 w = *(const float4*)&wr[j];
                float4 q = *(const float4*)&sQ[j];
                acc += w.x * q.x + w.y * q.y + w.z * q.z + w.w * q.w;
            }
            const float* vr = &whh[t * DIM];
#pragma unroll
            for (int j = 0; j < DIM; j += 4) {
                float4 w = *(const float4*)&vr[j];
                float4 h = *(const float4*)&sHl[j];
                acc += w.x * h.x + w.y * h.y + w.z * h.z + w.w * h.w;
            }
            sGate[t] = acc;
        }
        __syncthreads();
        if (t < 64) {
            float ig = fsig(sGate[t]);
            float fg = fsig(sGate[64 + t]);
            float gg = ftanh(sGate[128 + t]);
            float og = fsig(sGate[192 + t]);
            float c = fg * sCl[t] + ig * gg;
            sCl[t] = c;
            sHl[t] = og * ftanh(c);
        }
        __syncthreads();

        float mx = -1e30f;
        for (int j = t; j < cnt; j += 256) {
            float v = 0.0f;
            if (j < CAP) {
                const float* fr = &sF[j * FS];
#pragma unroll 8
                for (int dd = 0; dd < DIM; dd++) v += fr[dd] * sHl[dd];
                sE[j] = v;
            } else {
                const float* fr = &feat[(s0 + j) * DIM];
                for (int dd = 0; dd < DIM; dd++) v += fr[dd] * sHl[dd];
                g_e[s0 + j] = v;
            }
            mx = fmaxf(mx, v);
        }
        sRed[t] = mx;
        __syncthreads();
        for (int off = 128; off > 0; off >>= 1) {
            if (t < off) sRed[t] = fmaxf(sRed[t], sRed[t + off]);
            __syncthreads();
        }
        float emax = (cnt > 0) ? sRed[0] : 0.0f;
        __syncthreads();

        float sme = 0.0f;
        for (int j = t; j < cnt; j += 256) {
            float e = (j < CAP) ? sE[j] : g_e[s0 + j];
            sme += __expf(e - emax);
        }
        sRed[t] = sme;
        __syncthreads();
        for (int off = 128; off > 0; off >>= 1) {
            if (t < off) sRed[t] += sRed[t + off];
            __syncthreads();
        }
        float scale = __fdividef(1.0f, sRed[0] + 1e-16f);
        __syncthreads();
        for (int j = t; j < cnt; j += 256) {
            if (j < CAP) sE[j] = __expf(sE[j] - emax) * scale;
            else g_e[s0 + j] = __expf(g_e[s0 + j] - emax) * scale;
        }
        __syncthreads();

        {
            int d = t & 63, q = t >> 6;
            float acc = 0.0f;
            for (int j = q; j < cnt; j += 4) {
                float a = (j < CAP) ? sE[j] : g_e[s0 + j];
                float fv = (j < CAP) ? sF[j * FS + d] : feat[(s0 + j) * DIM + d];
                acc += a * fv;
            }
            sRed[t] = acc;
        }
        __syncthreads();
        if (t < 64) {
            float r = sRed[t] + sRed[64 + t] + sRed[128 + t] + sRed[192 + t];
            if (step == 2) {
                out[b * 2 * DIM + t] = sHl[t];
                out[b * 2 * DIM + DIM + t] = r;
            } else {
                sQ[t] = sHl[t];
                sQ[DIM + t] = r;
            }
        }
        __syncthreads();
    }
}

// ---------------- launch ----------------
extern "C" void kernel_launch(void* const* d_in, const int* in_sizes, int n_in,
                              void* d_out, int out_size) {
    const float* x        = (const float*)d_in[0];
    const int*   ei       = (const int*)d_in[1];
    const int*   batch    = (const int*)d_in[2];
    const float* lin0_w   = (const float*)d_in[3];
    const float* lin0_b   = (const float*)d_in[4];
    const float* nn1_w    = (const float*)d_in[5];
    const float* nn1_b    = (const float*)d_in[6];
    const float* nn2_w    = (const float*)d_in[7];
    const float* nn2_b    = (const float*)d_in[8];
    const float* conv_b   = (const float*)d_in[9];
    const float* gru_w_ih = (const float*)d_in[10];
    const float* gru_w_hh = (const float*)d_in[11];
    const float* gru_b_ih = (const float*)d_in[12];
    const float* gru_b_hh = (const float*)d_in[13];
    const float* lstm_w_ih = (const float*)d_in[14];
    const float* lstm_w_hh = (const float*)d_in[15];
    const float* lstm_b_ih = (const float*)d_in[16];
    const float* lstm_b_hh = (const float*)d_in[17];

    int N = in_sizes[2];
    int E = in_sizes[1] / 2;
    int B = (out_size - N * DIM) / (2 * DIM);

    float* out  = (float*)d_out;
    float* feat = out + B * 2 * DIM;

    float* feat2 = nullptr;
    cudaGetSymbolAddress((void**)&feat2, g_feat2);

    const int* src = ei;
    const int* dst = ei + E;

    const size_t smem_iter = SMEM_ITER_FLOATS * sizeof(float);
    const size_t smem_s2s  = SMEM_S2S_FLOATS * sizeof(float);
    cudaFuncSetAttribute(k_iter, cudaFuncAttributeMaxDynamicSharedMemorySize, (int)smem_iter);
    cudaFuncSetAttribute(k_set2set, cudaFuncAttributeMaxDynamicSharedMemorySize, (int)smem_s2s);

    int mx1 = (N > DIM * DIM ? N : DIM * DIM);
    int mx2 = (E > N ? E : N);

    // 0: EW + zero deg + gstart init
    k_init<<<(mx1 + 1023) / 1024, 1024>>>(nn1_w, nn1_b, nn2_w, nn2_b, N, B);
    // 1: ELL adjacency insert + graph-start marks
    k_count<<<(mx2 + 1023) / 1024, 1024>>>(src, dst, batch, E, N);
    // 2: lin0 (+ gstart fix)
    k_lin0<<<148, 256>>>(x, lin0_w, lin0_b, feat2, N, B);

    // 3..5: fused gather + NNConv + GRU  (index 3 gets profiled)
    k_iter<<<148, 1024, smem_iter>>>(feat2, feat, gru_w_ih, gru_w_hh, gru_b_ih, gru_b_hh, conv_b, N);
    k_iter<<<148, 1024, smem_iter>>>(feat, feat2, gru_w_ih, gru_w_hh, gru_b_ih, gru_b_hh, conv_b, N);
    k_iter<<<148, 1024, smem_iter>>>(feat2, feat, gru_w_ih, gru_w_hh, gru_b_ih, gru_b_hh, conv_b, N);

    // 6: fused Set2Set
    k_set2set<<<B, 256, smem_s2s>>>(feat, lstm_w_ih, lstm_w_hh, lstm_b_ih, lstm_b_hh, out);
}